// round 8
// baseline (speedup 1.0000x reference)
#include <cuda_runtime.h>

#define N_NODES 100000
#define D_FEAT  128
#define MAX_E   600000
#define NB2     888      // fused kernel grid: one wave at 6 CTAs/SM (148*6)
#define NBC     1184     // convert grid
#define TPB     256
#define MAXC    8192
#define QSCALE  16.0f
// int-score margin: 8 score-units * 256 (=s^2). Worst pairwise quant error ~3 units.
#define MARGIN_INT 2048

// Scratch (static __device__ — no allocation allowed)
__device__ __align__(128) unsigned g_h8[N_NODES * D_FEAT / 4]; // int8 rows, 128B each
__device__ int      g_score[MAX_E];               // coarse int scores (exact)
__device__ int      g_blockmin[NB2];
__device__ int      g_cand[MAXC];
__device__ float    g_cand_score[MAXC];
__device__ int      g_ncand;
__device__ int      g_bar;     // grid-barrier arrival counter
__device__ int      g_done;    // last-block election for rescore

__device__ __forceinline__ unsigned q4(float4 f) {
    int q0 = __float2int_rn(fminf(fmaxf(f.x * QSCALE, -127.f), 127.f));
    int q1 = __float2int_rn(fminf(fmaxf(f.y * QSCALE, -127.f), 127.f));
    int q2 = __float2int_rn(fminf(fmaxf(f.z * QSCALE, -127.f), 127.f));
    int q3 = __float2int_rn(fminf(fmaxf(f.w * QSCALE, -127.f), 127.f));
    return (unsigned)(q0 & 0xFF) | ((unsigned)(q1 & 0xFF) << 8) |
           ((unsigned)(q2 & 0xFF) << 16) | ((unsigned)q3 << 24);
}

// 16-byte int8 chunk dot via 4x dp4a (signed).
__device__ __forceinline__ int dot_i8_16B(uint4 ua, uint4 ub, int acc) {
    acc = __dp4a((int)ua.x, (int)ub.x, acc);
    acc = __dp4a((int)ua.y, (int)ub.y, acc);
    acc = __dp4a((int)ua.z, (int)ub.z, acc);
    acc = __dp4a((int)ua.w, (int)ub.w, acc);
    return acc;
}

// K1: f32 -> int8 quantization of h (q = round(16*h), clamp). Resets counters.
__global__ void convert_kernel(const float* __restrict__ h, int n16) {
    if (blockIdx.x == 0 && threadIdx.x == 0) { g_ncand = 0; g_bar = 0; g_done = 0; }
    const float4* __restrict__ h4 = (const float4*)h;
    uint4* __restrict__ o16 = (uint4*)g_h8;
    const int stride = gridDim.x * blockDim.x;
    for (int i = blockIdx.x * blockDim.x + threadIdx.x; i < n16; i += stride) {
        float4 f0 = h4[i * 4 + 0];
        float4 f1 = h4[i * 4 + 1];
        float4 f2 = h4[i * 4 + 2];
        float4 f3 = h4[i * 4 + 3];
        uint4 o;
        o.x = q4(f0);
        o.y = q4(f1);
        o.z = q4(f2);
        o.w = q4(f3);
        o16[i] = o;
    }
}

// K2 (fused, persistent single wave, 6 CTAs/SM):
//   Phase A: coarse int8 dp4a scores, 2 edges in flight per 8-lane group.
//   Grid barrier (all 888 blocks resident by construction).
//   Phase B: gmin reduce, out=1 + candidate select, last-block exact rescore.
__global__ void __launch_bounds__(TPB, 6)
score_finalize_kernel(const float* __restrict__ h,
                      const int* __restrict__ src,
                      const int* __restrict__ dst,
                      float* __restrict__ out, int E) {
    __shared__ int  smi[TPB / 32];
    __shared__ float smf[TPB / 32];
    __shared__ bool s_last;
    const int lane = threadIdx.x & 31;
    const int wid  = threadIdx.x >> 5;
    const unsigned gl    = lane & 7;
    const unsigned gmask = 0xFFu << (lane & 24);   // this 8-lane group's mask
    const int gid  = (blockIdx.x * blockDim.x + threadIdx.x) >> 3;
    const int nG   = (gridDim.x * blockDim.x) >> 3;
    const uint4* __restrict__ h8 = (const uint4*)g_h8;   // row = 8 x uint4 = 128B

    // ---- Phase A: coarse scoring, 2 edges per iteration ----
    int lmin = 0x7FFFFFFF;
    for (int e = gid; e < E; e += 2 * nG) {
        const int e2 = e + nG;
        const bool has2 = (e2 < E);
        const unsigned s0 = (unsigned)src[e];
        const unsigned d0 = (unsigned)dst[e];
        const unsigned s1 = has2 ? (unsigned)src[e2] : s0;
        const unsigned d1 = has2 ? (unsigned)dst[e2] : d0;
        uint4 ua0 = h8[s0 * 8u + gl];
        uint4 ub0 = h8[d0 * 8u + gl];
        uint4 ua1 = h8[s1 * 8u + gl];
        uint4 ub1 = h8[d1 * 8u + gl];

        int c0 = dot_i8_16B(ua0, ub0, 0);
        int c1 = dot_i8_16B(ua1, ub1, 0);
        c0 = __reduce_add_sync(gmask, c0);
        c1 = __reduce_add_sync(gmask, c1);
        if (gl == 0) {
            g_score[e] = c0;
            if (has2) g_score[e2] = c1;
        }
        lmin = min(lmin, c0);
        if (has2) lmin = min(lmin, c1);
    }

    lmin = __reduce_min_sync(0xFFFFFFFFu, lmin);
    if (lane == 0) smi[wid] = lmin;
    __syncthreads();
    if (threadIdx.x == 0) {
        int m = smi[0];
        #pragma unroll
        for (int i = 1; i < TPB / 32; i++) m = min(m, smi[i]);
        g_blockmin[blockIdx.x] = m;
    }

    // ---- Grid barrier (safe: NB2 = one full wave, all blocks resident) ----
    __threadfence();
    __syncthreads();
    if (threadIdx.x == 0) {
        atomicAdd(&g_bar, 1);
        while (*(volatile int*)&g_bar < (int)gridDim.x) __nanosleep(64);
    }
    __syncthreads();

    // ---- Phase B: gmin, out=1, candidate select ----
    int m = 0x7FFFFFFF;
    for (int i = threadIdx.x; i < NB2; i += blockDim.x)
        m = min(m, g_blockmin[i]);
    m = __reduce_min_sync(0xFFFFFFFFu, m);
    if (lane == 0) smi[wid] = m;
    __syncthreads();
    int gmin = smi[0];
    #pragma unroll
    for (int i = 1; i < TPB / 32; i++) gmin = min(gmin, smi[i]);
    const int thresh = gmin + MARGIN_INT;
    __syncthreads();

    const int nth = gridDim.x * blockDim.x;
    for (int e = blockIdx.x * blockDim.x + threadIdx.x; e < E; e += nth) {
        out[e] = 1.0f;
        if (g_score[e] <= thresh) {
            int idx = atomicAdd(&g_ncand, 1);
            if (idx < MAXC) g_cand[idx] = e;
        }
    }

    // ---- Last block: exact fp32 rescore of candidates, mark true min ----
    __threadfence();
    if (threadIdx.x == 0) {
        int t = atomicAdd(&g_done, 1);
        s_last = (t == (int)gridDim.x - 1);
    }
    __syncthreads();
    if (!s_last) return;

    const int nc = min(g_ncand, MAXC);
    float wmin = 3.4e38f;
    for (int i = wid; i < nc; i += TPB / 32) {     // warp per candidate
        const int ce = g_cand[i];
        float4 a = ((const float4*)(h + (long long)src[ce] * D_FEAT))[lane];
        float4 b = ((const float4*)(h + (long long)dst[ce] * D_FEAT))[lane];
        float acc = a.x * b.x + a.y * b.y + a.z * b.z + a.w * b.w;
        #pragma unroll
        for (int off = 16; off; off >>= 1)
            acc += __shfl_xor_sync(0xFFFFFFFFu, acc, off);
        if (lane == 0) g_cand_score[i] = acc;
        wmin = fminf(wmin, acc);
    }
    if (lane == 0) smf[wid] = wmin;
    __syncthreads();
    float gm = smf[0];
    #pragma unroll
    for (int i = 1; i < TPB / 32; i++) gm = fminf(gm, smf[i]);

    for (int i = threadIdx.x; i < nc; i += blockDim.x)
        if (g_cand_score[i] == gm) out[g_cand[i]] = 0.0f;
}

extern "C" void kernel_launch(void* const* d_in, const int* in_sizes, int n_in,
                              void* d_out, int out_size) {
    const float* h   = (const float*)d_in[0];
    const int*   src = (const int*)d_in[1];
    const int*   dst = (const int*)d_in[2];
    float* out = (float*)d_out;

    const int E   = in_sizes[1];
    const int n16 = N_NODES * D_FEAT / 16;   // uint4 outputs

    convert_kernel<<<NBC, TPB>>>(h, n16);
    score_finalize_kernel<<<NB2, TPB>>>(h, src, dst, out, E);
}

// round 9
// speedup vs baseline: 1.0009x; 1.0009x over previous
#include <cuda_runtime.h>

#define N_NODES 100000
#define D_FEAT  128
#define MAX_E   600000
#define GRID    592      // one wave: 148 SMs x 4 CTAs (guaranteed by launch_bounds)
#define TPB     256
#define MAXC    8192
#define QSCALE  16.0f
// int-score margin: 8 score-units * 256 (=16^2). Worst pairwise quant error ~3 units.
#define MARGIN_INT 2048

// Scratch (static __device__ — no allocation allowed). Zero-init on load;
// counters are self-reset by the last block each call.
__device__ __align__(128) unsigned g_h8[N_NODES * D_FEAT / 4]; // int8 rows, 128B each
__device__ int      g_score[MAX_E];
__device__ int      g_blockmin[GRID];
__device__ int      g_cand[MAXC];
__device__ float    g_cand_score[MAXC];
__device__ int      g_ncand;
__device__ int      g_bar;     // monotonic grid-barrier counter (used twice/call)
__device__ int      g_done;    // last-block election

__device__ __forceinline__ unsigned q4(float4 f) {
    int q0 = __float2int_rn(fminf(fmaxf(f.x * QSCALE, -127.f), 127.f));
    int q1 = __float2int_rn(fminf(fmaxf(f.y * QSCALE, -127.f), 127.f));
    int q2 = __float2int_rn(fminf(fmaxf(f.z * QSCALE, -127.f), 127.f));
    int q3 = __float2int_rn(fminf(fmaxf(f.w * QSCALE, -127.f), 127.f));
    return (unsigned)(q0 & 0xFF) | ((unsigned)(q1 & 0xFF) << 8) |
           ((unsigned)(q2 & 0xFF) << 16) | ((unsigned)q3 << 24);
}

__device__ __forceinline__ int dot_i8_16B(uint4 ua, uint4 ub) {
    int acc = __dp4a((int)ua.x, (int)ub.x, 0);
    acc = __dp4a((int)ua.y, (int)ub.y, acc);
    acc = __dp4a((int)ua.z, (int)ub.z, acc);
    acc = __dp4a((int)ua.w, (int)ub.w, acc);
    return acc;
}

__device__ __forceinline__ void grid_barrier(int target) {
    __threadfence();
    __syncthreads();
    if (threadIdx.x == 0) {
        atomicAdd(&g_bar, 1);
        while (*(volatile int*)&g_bar < target) __nanosleep(64);
    }
    __syncthreads();
}

// Single persistent kernel:
//   Phase 0: f32 -> int8 quantize h            (grid barrier)
//   Phase A: coarse dp4a scores, 4-edge software-pipelined   (grid barrier)
//   Phase B: gmin, out=1, candidate select; last block exact rescore + reset.
__global__ void __launch_bounds__(TPB, 4)
fused_kernel(const float* __restrict__ h,
             const int* __restrict__ src,
             const int* __restrict__ dst,
             float* __restrict__ out, int E) {
    __shared__ int   smi[TPB / 32];
    __shared__ float smf[TPB / 32];
    __shared__ bool  s_last;
    const int lane = threadIdx.x & 31;
    const int wid  = threadIdx.x >> 5;
    const unsigned gl    = lane & 7;
    const unsigned gmask = 0xFFu << (lane & 24);
    const int gid  = (blockIdx.x * TPB + threadIdx.x) >> 3;
    const int nG   = (GRID * TPB) >> 3;

    // ---- Phase 0: quantize h to int8 rows ----
    {
        const float4* __restrict__ h4 = (const float4*)h;
        uint4* __restrict__ o16 = (uint4*)g_h8;
        const int n16 = N_NODES * D_FEAT / 16;
        const int stride = GRID * TPB;
        for (int i = blockIdx.x * TPB + threadIdx.x; i < n16; i += stride) {
            float4 f0 = h4[i * 4 + 0];
            float4 f1 = h4[i * 4 + 1];
            float4 f2 = h4[i * 4 + 2];
            float4 f3 = h4[i * 4 + 3];
            uint4 o;
            o.x = q4(f0); o.y = q4(f1); o.z = q4(f2); o.w = q4(f3);
            o16[i] = o;
        }
    }
    grid_barrier(GRID);

    // ---- Phase A: coarse scoring, 4 edges/iter, index prefetch pipeline ----
    const uint4* __restrict__ h8 = (const uint4*)g_h8;   // row = 8 x uint4 = 128B
    int lmin = 0x7FFFFFFF;
    {
        const int step = 4 * nG;
        int e = gid;
        unsigned s[4], d[4];
        #pragma unroll
        for (int k = 0; k < 4; k++) {
            int ek = e + k * nG;
            bool v = (ek < E);
            s[k] = v ? (unsigned)src[ek] : 0u;
            d[k] = v ? (unsigned)dst[ek] : 0u;
        }
        while (e < E) {
            // Issue all gathers for the current batch (8 loads in flight).
            uint4 ua[4], ub[4];
            #pragma unroll
            for (int k = 0; k < 4; k++) {
                ua[k] = h8[s[k] * 8u + gl];
                ub[k] = h8[d[k] * 8u + gl];
            }
            bool v[4];
            #pragma unroll
            for (int k = 0; k < 4; k++) v[k] = (e + k * nG < E);

            // Prefetch next batch indices while gathers are in flight.
            const int en = e + step;
            #pragma unroll
            for (int k = 0; k < 4; k++) {
                int ek = en + k * nG;
                bool vn = (ek < E);
                s[k] = vn ? (unsigned)src[ek] : 0u;
                d[k] = vn ? (unsigned)dst[ek] : 0u;
            }

            // Consume gathers.
            #pragma unroll
            for (int k = 0; k < 4; k++) {
                int c = dot_i8_16B(ua[k], ub[k]);
                c = __reduce_add_sync(gmask, c);
                if (v[k]) {
                    if (gl == 0) g_score[e + k * nG] = c;
                    lmin = min(lmin, c);
                }
            }
            e = en;
        }
    }

    lmin = __reduce_min_sync(0xFFFFFFFFu, lmin);
    if (lane == 0) smi[wid] = lmin;
    __syncthreads();
    if (threadIdx.x == 0) {
        int m = smi[0];
        #pragma unroll
        for (int i = 1; i < TPB / 32; i++) m = min(m, smi[i]);
        g_blockmin[blockIdx.x] = m;
    }
    grid_barrier(2 * GRID);

    // ---- Phase B: gmin, out=1, candidate select ----
    int m = 0x7FFFFFFF;
    for (int i = threadIdx.x; i < GRID; i += TPB)
        m = min(m, g_blockmin[i]);
    m = __reduce_min_sync(0xFFFFFFFFu, m);
    if (lane == 0) smi[wid] = m;
    __syncthreads();
    int gmin = smi[0];
    #pragma unroll
    for (int i = 1; i < TPB / 32; i++) gmin = min(gmin, smi[i]);
    const int thresh = gmin + MARGIN_INT;
    __syncthreads();

    const int nth = GRID * TPB;
    for (int e = blockIdx.x * TPB + threadIdx.x; e < E; e += nth) {
        out[e] = 1.0f;
        if (g_score[e] <= thresh) {
            int idx = atomicAdd(&g_ncand, 1);
            if (idx < MAXC) g_cand[idx] = e;
        }
    }

    // ---- Last block: exact fp32 rescore, mark true min, reset counters ----
    __threadfence();
    if (threadIdx.x == 0) {
        int t = atomicAdd(&g_done, 1);
        s_last = (t == GRID - 1);
    }
    __syncthreads();
    if (!s_last) return;

    const int nc = min(g_ncand, MAXC);
    float wmin = 3.4e38f;
    for (int i = wid; i < nc; i += TPB / 32) {     // warp per candidate
        const int ce = g_cand[i];
        float4 a = ((const float4*)(h + (long long)src[ce] * D_FEAT))[lane];
        float4 b = ((const float4*)(h + (long long)dst[ce] * D_FEAT))[lane];
        float acc = a.x * b.x + a.y * b.y + a.z * b.z + a.w * b.w;
        #pragma unroll
        for (int off = 16; off; off >>= 1)
            acc += __shfl_xor_sync(0xFFFFFFFFu, acc, off);
        if (lane == 0) g_cand_score[i] = acc;
        wmin = fminf(wmin, acc);
    }
    if (lane == 0) smf[wid] = wmin;
    __syncthreads();
    float gm = smf[0];
    #pragma unroll
    for (int i = 1; i < TPB / 32; i++) gm = fminf(gm, smf[i]);

    for (int i = threadIdx.x; i < nc; i += TPB)
        if (g_cand_score[i] == gm) out[g_cand[i]] = 0.0f;

    // Self-reset for the next call / graph replay (all other blocks are done
    // with these counters by construction of the g_done election).
    __syncthreads();
    if (threadIdx.x == 0) { g_bar = 0; g_done = 0; g_ncand = 0; }
    __threadfence();
}

extern "C" void kernel_launch(void* const* d_in, const int* in_sizes, int n_in,
                              void* d_out, int out_size) {
    const float* h   = (const float*)d_in[0];
    const int*   src = (const int*)d_in[1];
    const int*   dst = (const int*)d_in[2];
    float* out = (float*)d_out;

    const int E = in_sizes[1];

    fused_kernel<<<GRID, TPB>>>(h, src, dst, out, E);
}